// round 8
// baseline (speedup 1.0000x reference)
#include <cuda_runtime.h>
#include <cuda_bf16.h>

// HintGenKernelBatched: masked XOR-parity gather-reduce.
//   entries:        [1000000, 5]  int32
//   padded_indices: [4096, 2048]  int32 in [0, 1e6)
//   valid_mask:     [4096, 2048]  int32 in {0, 1}
//   out:            [4096, 5]     float32 (numeric convert; values < 2^31)
//
// R7: no unit >53% -> latency-bound; only deleting real bytes/wavefronts helps.
// This version pads the table to 32B rows (pre-pass into __device__ scratch),
// making every gathered row exactly ONE 32B sector, 16B-aligned. Main kernel
// gathers with 2-lane groups doing LDG.128 each (lane0: words0-3, lane1:
// word4+pad), 4 rows per group per int4 of indices -> 4 unrolled iterations.

#define MAX_SUBSET 2048
#define ROW 5
#define THREADS 256
#define MAX_ENTRIES 1000000

// Padded table: 2 int4 per row (words 0..4 + 3 pad words). 32 MB static scratch.
__device__ __align__(32) int4 g_pad[2 * MAX_ENTRIES];

__global__ __launch_bounds__(256) void pad_entries_kernel(
    const int* __restrict__ entries, int n)
{
    const int i = blockIdx.x * blockDim.x + threadIdx.x;
    if (i < n) {
        const int* __restrict__ r = entries + (size_t)i * ROW;
        int4 a, b;
        a.x = __ldg(r + 0); a.y = __ldg(r + 1);
        a.z = __ldg(r + 2); a.w = __ldg(r + 3);
        b.x = __ldg(r + 4); b.y = 0; b.z = 0; b.w = 0;
        g_pad[2 * (size_t)i + 0] = a;   // STG.128, coalesced (32B row stride)
        g_pad[2 * (size_t)i + 1] = b;
    }
}

__global__ __launch_bounds__(THREADS, 8) void hint_parity_kernel(
    const int* __restrict__ padded_indices,
    const int* __restrict__ valid_mask,
    float* __restrict__ out)
{
    __shared__ int4 sidx4[MAX_SUBSET / 4];      // masked indices, -1 = invalid
    __shared__ unsigned red[THREADS / 32][ROW];

    const int h = blockIdx.x;
    const int t = threadIdx.x;
    const size_t base = (size_t)h * MAX_SUBSET;

    const int4* __restrict__ idx4 = reinterpret_cast<const int4*>(padded_indices + base);
    const int4* __restrict__ msk4 = reinterpret_cast<const int4*>(valid_mask + base);

    // ---- Phase 1: coalesced stream + mask fold into smem ----
    #pragma unroll
    for (int p = 0; p < MAX_SUBSET / (THREADS * 4); ++p) {
        const int4 iv = idx4[p * THREADS + t];
        const int4 mv = msk4[p * THREADS + t];
        int4 o;
        o.x = mv.x ? iv.x : -1;
        o.y = mv.y ? iv.y : -1;
        o.z = mv.z ? iv.z : -1;
        o.w = mv.w ? iv.w : -1;
        sidx4[p * THREADS + t] = o;             // STS.128, conflict-free
    }
    __syncthreads();

    // ---- Phase 2: 2-lane groups, LDG.128 per lane, 4 rows per index-int4 ----
    const int lane = t & 31;
    const int warp = t >> 5;
    const int g    = t >> 1;                    // group id 0..127
    const int j    = t & 1;                     // int4-within-row (0: w0-3, 1: w4+pad)

    int4 acc = make_int4(0, 0, 0, 0);           // lane1's acc.yzw are dead pad

    #pragma unroll
    for (int p = 0; p < MAX_SUBSET / 4 / (THREADS / 2); ++p) {   // 4 iterations
        const int4 q = sidx4[p * (THREADS / 2) + g];  // LDS.128, pair-broadcast

        #define GATHERW(I)                                                     \
            if ((I) >= 0) {                                                    \
                const int4 v = __ldg(&g_pad[2 * (size_t)(unsigned)(I) + j]);   \
                acc.x ^= v.x; acc.y ^= v.y; acc.z ^= v.z; acc.w ^= v.w;        \
            }

        GATHERW(q.x)
        GATHERW(q.y)
        GATHERW(q.z)
        GATHERW(q.w)
        #undef GATHERW
    }

    // ---- Reduce across the 16 groups of each warp (parity-preserving) ----
    #pragma unroll
    for (int o = 2; o <= 16; o <<= 1) {
        acc.x ^= __shfl_xor_sync(0xffffffffu, acc.x, o);
        acc.y ^= __shfl_xor_sync(0xffffffffu, acc.y, o);
        acc.z ^= __shfl_xor_sync(0xffffffffu, acc.z, o);
        acc.w ^= __shfl_xor_sync(0xffffffffu, acc.w, o);
    }

    // lane0: warp parity words 0-3; lane1: word 4 in acc.x
    if (lane == 0) {
        red[warp][0] = (unsigned)acc.x;
        red[warp][1] = (unsigned)acc.y;
        red[warp][2] = (unsigned)acc.z;
        red[warp][3] = (unsigned)acc.w;
    }
    if (lane == 1) {
        red[warp][4] = (unsigned)acc.x;
    }
    __syncthreads();

    // ---- Fold 8 warps, store float32 ----
    if (t < ROW) {
        unsigned v = red[0][t];
        #pragma unroll
        for (int w = 1; w < THREADS / 32; ++w) v ^= red[w][t];
        out[(size_t)h * ROW + t] = (float)v;    // numeric convert, values < 2^31
    }
}

extern "C" void kernel_launch(void* const* d_in, const int* in_sizes, int n_in,
                              void* d_out, int out_size)
{
    const int* entries        = (const int*)d_in[0];
    const int* padded_indices = (const int*)d_in[1];
    const int* valid_mask     = (const int*)d_in[2];
    float* out = (float*)d_out;

    int n_entries = in_sizes[0] / ROW;          // 1,000,000
    if (n_entries > MAX_ENTRIES) n_entries = MAX_ENTRIES;
    const int num_hints = out_size / ROW;       // 4096

    pad_entries_kernel<<<(n_entries + 255) / 256, 256>>>(entries, n_entries);
    hint_parity_kernel<<<num_hints, THREADS>>>(padded_indices, valid_mask, out);
}

// round 9
// speedup vs baseline: 1.1839x; 1.1839x over previous
#include <cuda_runtime.h>
#include <cuda_bf16.h>

// HintGenKernelBatched: masked XOR-parity gather-reduce.
//   entries:        [1000000, 5]  int32
//   padded_indices: [4096, 2048]  int32 in [0, 1e6)
//   valid_mask:     [4096, 2048]  int32 in {0, 1}
//   out:            [4096, 5]     float32 (numeric convert; values < 2^31)
//
// R8 post-mortem: padded-table pre-pass FAILED (cost > gain). Reverted.
// New evidence: HBM/launch ~81MB > 64MB streamed -> the 20MB entries table is
// being partially evicted from L2 each replay by the zero-reuse index/mask
// stream. Fix via cache policy only:
//   - streamed loads  : ld.global.cs (evict-first; don't thrash the table)
//   - gather loads    : ld.global.cg (L2-only; skip useless L1 allocation)
// Structure = R6/R7 hybrid: 8-lane group per row, int4-LDS gives 4 rows per
// group-iteration, predicated scalar gathers, shfl+smem XOR reduction.

#define MAX_SUBSET 2048
#define ROW 5
#define THREADS 256
#define NGROUPS (THREADS / 8)                   // 32 row-gather groups per CTA
#define NITER (MAX_SUBSET / 4 / NGROUPS)        // 16 int4-iterations per group

__device__ __forceinline__ int4 ldcs_int4(const int4* p) {
    int4 v;
    asm("ld.global.cs.v4.u32 {%0,%1,%2,%3}, [%4];"
        : "=r"(v.x), "=r"(v.y), "=r"(v.z), "=r"(v.w) : "l"(p));
    return v;
}

__device__ __forceinline__ unsigned ldcg_u32(const int* p) {
    unsigned v;
    asm("ld.global.cg.u32 %0, [%1];" : "=r"(v) : "l"(p));
    return v;
}

__global__ __launch_bounds__(THREADS, 8) void hint_parity_kernel(
    const int* __restrict__ entries,
    const int* __restrict__ padded_indices,
    const int* __restrict__ valid_mask,
    float* __restrict__ out)
{
    __shared__ int4 sidx4[MAX_SUBSET / 4];      // masked indices, -1 = invalid
    __shared__ unsigned red[THREADS / 32][ROW];

    const int h = blockIdx.x;
    const int t = threadIdx.x;
    const size_t base = (size_t)h * MAX_SUBSET;

    const int4* __restrict__ idx4 = reinterpret_cast<const int4*>(padded_indices + base);
    const int4* __restrict__ msk4 = reinterpret_cast<const int4*>(valid_mask + base);

    // ---- Phase 1: coalesced evict-first stream + mask fold into smem ----
    #pragma unroll
    for (int p = 0; p < MAX_SUBSET / (THREADS * 4); ++p) {
        const int4 iv = ldcs_int4(idx4 + p * THREADS + t);
        const int4 mv = ldcs_int4(msk4 + p * THREADS + t);
        int4 o;
        o.x = mv.x ? iv.x : -1;
        o.y = mv.y ? iv.y : -1;
        o.z = mv.z ? iv.z : -1;
        o.w = mv.w ? iv.w : -1;
        sidx4[p * THREADS + t] = o;             // STS.128, conflict-free
    }
    __syncthreads();

    // ---- Phase 2: cooperative gather, one 8-lane group per row,
    //      4 rows per LDS.128 of indices, L2-only gather loads ----
    const int lane = t & 31;
    const int warp = t >> 5;
    const int g    = t >> 3;                    // group id 0..31
    const int j    = t & 7;                     // word-within-row (j<5 active)
    const bool wlane = (j < ROW);

    unsigned acc = 0;

    #pragma unroll
    for (int p = 0; p < NITER; ++p) {
        const int4 q = sidx4[p * NGROUPS + g];  // LDS.128 broadcast within group

        if (wlane) {
            if (q.x >= 0) acc ^= ldcg_u32(entries + (size_t)(unsigned)q.x * ROW + j);
            if (q.y >= 0) acc ^= ldcg_u32(entries + (size_t)(unsigned)q.y * ROW + j);
            if (q.z >= 0) acc ^= ldcg_u32(entries + (size_t)(unsigned)q.z * ROW + j);
            if (q.w >= 0) acc ^= ldcg_u32(entries + (size_t)(unsigned)q.w * ROW + j);
        }
    }

    // ---- Reduce the 4 groups of each warp (lanes with equal t&7 combine) ----
    acc ^= __shfl_xor_sync(0xffffffffu, acc, 8);
    acc ^= __shfl_xor_sync(0xffffffffu, acc, 16);

    // lanes 0..4 of each warp now hold the warp's parity for words 0..4
    if (lane < ROW) red[warp][lane] = acc;
    __syncthreads();

    // ---- Fold 8 warps, store float32 ----
    if (t < ROW) {
        unsigned v = red[0][t];
        #pragma unroll
        for (int w = 1; w < THREADS / 32; ++w) v ^= red[w][t];
        out[(size_t)h * ROW + t] = (float)v;    // numeric convert, values < 2^31
    }
}

extern "C" void kernel_launch(void* const* d_in, const int* in_sizes, int n_in,
                              void* d_out, int out_size)
{
    const int* entries        = (const int*)d_in[0];
    const int* padded_indices = (const int*)d_in[1];
    const int* valid_mask     = (const int*)d_in[2];
    float* out = (float*)d_out;

    const int num_hints = out_size / ROW;  // 4096
    hint_parity_kernel<<<num_hints, THREADS>>>(entries, padded_indices, valid_mask, out);
}

// round 10
// speedup vs baseline: 1.4437x; 1.2195x over previous
#include <cuda_runtime.h>
#include <cuda_bf16.h>

// HintGenKernelBatched: masked XOR-parity gather-reduce.
//   entries:        [1000000, 5]  int32
//   padded_indices: [4096, 2048]  int32 in [0, 1e6)
//   valid_mask:     [4096, 2048]  int32 in {0, 1}
//   out:            [4096, 5]     float32 (numeric convert; values < 2^31)
//
// R6-R9: three gather geometries all 33.6us; no unit >53%. Invariants: L1
// wavefront floor (1 line per random row) and ~50% predicated-dead gather
// work (mask ~Bernoulli(1/2)). This version deletes the dead work:
//   Phase 1: warp-local ballot/popc COMPACTION of valid indices into smem.
//   Phase 2: DENSE cooperative gathers -- every LDG covers 4 valid rows,
//            ~1.3 instructions per gathered row, no per-slot mask predicate.
// XOR order is irrelevant, so compaction reordering is harmless.

#define MAX_SUBSET 2048
#define ROW 5
#define THREADS 256
#define WARPS (THREADS / 32)
#define SLOTS_PER_WARP (MAX_SUBSET / WARPS)     // 256
#define SEG 264                                 // 256 max valid + 4 sentinel + pad

__global__ __launch_bounds__(THREADS, 8) void hint_parity_kernel(
    const int* __restrict__ entries,
    const int* __restrict__ padded_indices,
    const int* __restrict__ valid_mask,
    float* __restrict__ out)
{
    __shared__ int scomp[WARPS][SEG];           // per-warp compacted indices
    __shared__ unsigned red[WARPS][ROW];

    const int h    = blockIdx.x;
    const int t    = threadIdx.x;
    const int warp = t >> 5;
    const int lane = t & 31;
    const size_t base = (size_t)h * MAX_SUBSET;

    const int4* __restrict__ idx4 =
        reinterpret_cast<const int4*>(padded_indices + base) + warp * (SLOTS_PER_WARP / 4);
    const int4* __restrict__ msk4 =
        reinterpret_cast<const int4*>(valid_mask + base) + warp * (SLOTS_PER_WARP / 4);

    // ---- Phase 1: stream + warp-local compaction (order irrelevant for XOR) ----
    unsigned cnt = 0;
    const unsigned lmask = (1u << lane) - 1u;

    #pragma unroll
    for (int i = 0; i < SLOTS_PER_WARP / (32 * 4); ++i) {   // 2 iterations
        const int4 iv = idx4[i * 32 + lane];                // LDG.128 coalesced
        const int4 mv = msk4[i * 32 + lane];

        #define COMPACT(IC, MC)                                          \
            {                                                            \
                const unsigned bal = __ballot_sync(0xffffffffu, (MC) != 0); \
                if (MC) scomp[warp][cnt + __popc(bal & lmask)] = (IC);   \
                cnt += __popc(bal);                                      \
            }
        COMPACT(iv.x, mv.x)
        COMPACT(iv.y, mv.y)
        COMPACT(iv.z, mv.z)
        COMPACT(iv.w, mv.w)
        #undef COMPACT
    }
    // sentinel pad so the dense loop can round up to multiple of 4
    if (lane < 4) scomp[warp][cnt + lane] = -1;
    __syncwarp();

    // ---- Phase 2: dense cooperative gather ----
    // 4 groups of 8 lanes; group g takes compacted slot it*4+g; lane j<5
    // loads word j of that row. Every LDG covers 4 valid rows (1 line each).
    const int j  = lane & 7;
    const int g  = lane >> 3;
    const bool wl = (j < ROW);

    unsigned acc = 0;
    const int nit = (int)((cnt + 3) >> 2);

    #pragma unroll 4
    for (int it = 0; it < nit; ++it) {
        const int q = scomp[warp][it * 4 + g];  // LDS.32, group-broadcast
        if (wl && q >= 0) {
            acc ^= (unsigned)__ldg(entries + (size_t)(unsigned)q * ROW + j);
        }
    }

    // ---- Reduce the 4 groups of each warp ----
    acc ^= __shfl_xor_sync(0xffffffffu, acc, 8);
    acc ^= __shfl_xor_sync(0xffffffffu, acc, 16);

    // lanes 0..4 hold the warp's parity for words 0..4
    if (lane < ROW) red[warp][lane] = acc;
    __syncthreads();

    // ---- Fold 8 warps, store float32 ----
    if (t < ROW) {
        unsigned v = red[0][t];
        #pragma unroll
        for (int w = 1; w < WARPS; ++w) v ^= red[w][t];
        out[(size_t)h * ROW + t] = (float)v;    // numeric convert, values < 2^31
    }
}

extern "C" void kernel_launch(void* const* d_in, const int* in_sizes, int n_in,
                              void* d_out, int out_size)
{
    const int* entries        = (const int*)d_in[0];
    const int* padded_indices = (const int*)d_in[1];
    const int* valid_mask     = (const int*)d_in[2];
    float* out = (float*)d_out;

    const int num_hints = out_size / ROW;  // 4096
    hint_parity_kernel<<<num_hints, THREADS>>>(entries, padded_indices, valid_mask, out);
}